// round 1
// baseline (speedup 1.0000x reference)
#include <cuda_runtime.h>

// Problem constants
#define B_ 4
#define L_ 1024
#define C_ 768
#define H_ 12
#define D_ 64
#define M_ (B_ * L_)      // 4096 rows of x
#define NQKV_ (3 * C_)    // 2304

// Scratch (device globals; no allocation allowed in kernel_launch)
__device__ float g_q[B_ * H_ * L_ * D_];   // [B,H,L,D]
__device__ float g_k[B_ * H_ * L_ * D_];
__device__ float g_v[B_ * H_ * L_ * D_];
__device__ float g_o[M_ * C_];             // attention output, [B*L, C]

// ---------------------------------------------------------------------------
// Kernel 1: QKV GEMM.  qkv[m,f] = sum_c x[m,c] * w_qkv[f,c]   (NT gemm)
// Tile 64x64, BK=16, 256 threads, 4x4 register micro-tile.
// Epilogue scatters directly into g_q/g_k/g_v in [B,H,L,D] layout.
// Because tiles are 64-aligned in f and D=64, each block maps to exactly one
// (t, h) pair and one batch b.
// ---------------------------------------------------------------------------
__global__ __launch_bounds__(256) void qkv_gemm(const float* __restrict__ x,
                                                const float* __restrict__ w)
{
    __shared__ float As[16 * 68];   // [k][m], padded
    __shared__ float Bs[16 * 68];   // [k][n], padded

    const int m0 = blockIdx.y * 64;
    const int n0 = blockIdx.x * 64;
    const int tid = threadIdx.x;
    const int ty = tid >> 4;        // 0..15
    const int tx = tid & 15;        // 0..15
    const int lm = tid >> 2;        // 0..63 (row within tile for loads)
    const int kq = (tid & 3) * 4;   // 0,4,8,12 (k offset for float4 load)

    float acc[4][4];
#pragma unroll
    for (int i = 0; i < 4; i++)
#pragma unroll
        for (int j = 0; j < 4; j++) acc[i][j] = 0.f;

    for (int k0 = 0; k0 < C_; k0 += 16) {
        float4 av = *(const float4*)&x[(size_t)(m0 + lm) * C_ + k0 + kq];
        float4 bv = *(const float4*)&w[(size_t)(n0 + lm) * C_ + k0 + kq];
        As[(kq + 0) * 68 + lm] = av.x;
        As[(kq + 1) * 68 + lm] = av.y;
        As[(kq + 2) * 68 + lm] = av.z;
        As[(kq + 3) * 68 + lm] = av.w;
        Bs[(kq + 0) * 68 + lm] = bv.x;
        Bs[(kq + 1) * 68 + lm] = bv.y;
        Bs[(kq + 2) * 68 + lm] = bv.z;
        Bs[(kq + 3) * 68 + lm] = bv.w;
        __syncthreads();
#pragma unroll
        for (int k = 0; k < 16; k++) {
            float4 a = *(const float4*)&As[k * 68 + 4 * ty];
            float4 b = *(const float4*)&Bs[k * 68 + 4 * tx];
            acc[0][0] += a.x * b.x; acc[0][1] += a.x * b.y; acc[0][2] += a.x * b.z; acc[0][3] += a.x * b.w;
            acc[1][0] += a.y * b.x; acc[1][1] += a.y * b.y; acc[1][2] += a.y * b.z; acc[1][3] += a.y * b.w;
            acc[2][0] += a.z * b.x; acc[2][1] += a.z * b.y; acc[2][2] += a.z * b.z; acc[2][3] += a.z * b.w;
            acc[3][0] += a.w * b.x; acc[3][1] += a.w * b.y; acc[3][2] += a.w * b.z; acc[3][3] += a.w * b.w;
        }
        __syncthreads();
    }

    // Epilogue scatter
    const int t  = n0 / C_;               // 0=q,1=k,2=v
    const int h  = (n0 % C_) / D_;        // head (tile is 64-aligned -> single h)
    const int bb = m0 / L_;
    const int l0 = m0 % L_;
    float* dst = (t == 0) ? g_q : (t == 1) ? g_k : g_v;
#pragma unroll
    for (int i = 0; i < 4; i++) {
        int l = l0 + 4 * ty + i;
        float4 v = make_float4(acc[i][0], acc[i][1], acc[i][2], acc[i][3]);
        *(float4*)&dst[((size_t)(bb * H_ + h) * L_ + l) * D_ + 4 * tx] = v;
    }
}

// ---------------------------------------------------------------------------
// Kernel 2: fused attention per (b,h).  One block = 32 query rows.
// Buffers the full 32x1024 score strip in dynamic smem so attn_score is
// written to HBM exactly once and never re-read for PV.
// ---------------------------------------------------------------------------
#define SSTR 1032   // padded row stride for score strip (1024 + 8)

__global__ __launch_bounds__(256) void attn_kernel(float* __restrict__ attn_out)
{
    extern __shared__ float sm[];
    float* Qs  = sm;                        // 32 * 68
    float* KVs = sm + 32 * 68;              // 64 * 68  (K^T, then V)
    float* Ss  = sm + 32 * 68 + 64 * 68;    // 32 * SSTR

    const int bh  = blockIdx.y;             // 0..47
    const int m0  = blockIdx.x * 32;        // row tile within L
    const int tid = threadIdx.x;
    const int ty  = tid >> 4;               // 0..15
    const int tx  = tid & 15;               // 0..15

    const size_t head_base = (size_t)bh * L_ * D_;
    const float* qb = g_q + head_base;
    const float* kb = g_k + head_base;
    const float* vb = g_v + head_base;
    const float scale = 0.125f;             // 1/sqrt(64)

    // Load Q tile [32][64] row-major
    {
        int i = tid;
#pragma unroll
        for (int r = 0; r < 2; r++, i += 256) {
            int row = i >> 4;
            int c4  = (i & 15) * 4;
            float4 v = *(const float4*)&qb[(size_t)(m0 + row) * D_ + c4];
            *(float4*)&Qs[row * 68 + c4] = v;
        }
    }

    // ---- Scores: S = scale * Q K^T, strip-buffered in smem ----
    for (int n0 = 0; n0 < L_; n0 += 64) {
        // Load K tile transposed: KVs[k][n]
        int i = tid;
#pragma unroll
        for (int r = 0; r < 4; r++, i += 256) {
            int n  = i >> 4;
            int k4 = (i & 15) * 4;
            float4 v = *(const float4*)&kb[(size_t)(n0 + n) * D_ + k4];
            KVs[(k4 + 0) * 68 + n] = v.x;
            KVs[(k4 + 1) * 68 + n] = v.y;
            KVs[(k4 + 2) * 68 + n] = v.z;
            KVs[(k4 + 3) * 68 + n] = v.w;
        }
        __syncthreads();

        float c0[4] = {0.f, 0.f, 0.f, 0.f};
        float c1[4] = {0.f, 0.f, 0.f, 0.f};
#pragma unroll
        for (int k = 0; k < 64; k++) {
            float a0 = Qs[(2 * ty) * 68 + k];
            float a1 = Qs[(2 * ty + 1) * 68 + k];
            float4 b = *(const float4*)&KVs[k * 68 + 4 * tx];
            c0[0] += a0 * b.x; c0[1] += a0 * b.y; c0[2] += a0 * b.z; c0[3] += a0 * b.w;
            c1[0] += a1 * b.x; c1[1] += a1 * b.y; c1[2] += a1 * b.z; c1[3] += a1 * b.w;
        }
        *(float4*)&Ss[(2 * ty) * SSTR + n0 + 4 * tx] =
            make_float4(c0[0] * scale, c0[1] * scale, c0[2] * scale, c0[3] * scale);
        *(float4*)&Ss[(2 * ty + 1) * SSTR + n0 + 4 * tx] =
            make_float4(c1[0] * scale, c1[1] * scale, c1[2] * scale, c1[3] * scale);
        __syncthreads();
    }

    // ---- Softmax: warp w handles rows 4w..4w+3, full-warp row reduce ----
    const int warp = tid >> 5;
    const int lane = tid & 31;
    float* attnb = attn_out + (size_t)bh * L_ * L_;
    for (int rr = 0; rr < 4; rr++) {
        int row = warp * 4 + rr;
        float* srow = &Ss[row * SSTR];
        float pv[32];
        float mx = -1e30f;
#pragma unroll
        for (int j = 0; j < 32; j++) {
            pv[j] = srow[lane + 32 * j];
            mx = fmaxf(mx, pv[j]);
        }
#pragma unroll
        for (int o = 16; o > 0; o >>= 1)
            mx = fmaxf(mx, __shfl_xor_sync(0xffffffffu, mx, o));
        float sum = 0.f;
#pragma unroll
        for (int j = 0; j < 32; j++) {
            pv[j] = __expf(pv[j] - mx);
            sum += pv[j];
        }
#pragma unroll
        for (int o = 16; o > 0; o >>= 1)
            sum += __shfl_xor_sync(0xffffffffu, sum, o);
        float inv = 1.0f / sum;
        float* grow = attnb + (size_t)(m0 + row) * L_;
#pragma unroll
        for (int j = 0; j < 32; j++) {
            float p = pv[j] * inv;
            srow[lane + 32 * j] = p;       // keep normalized P for PV
            grow[lane + 32 * j] = p;       // materialize attn_score
        }
    }
    __syncthreads();

    // ---- PV: O = P V, accumulate over column tiles ----
    float o0[4] = {0.f, 0.f, 0.f, 0.f};
    float o1[4] = {0.f, 0.f, 0.f, 0.f};
    for (int n0 = 0; n0 < L_; n0 += 64) {
        int i = tid;
#pragma unroll
        for (int r = 0; r < 4; r++, i += 256) {
            int n  = i >> 4;
            int k4 = (i & 15) * 4;
            float4 v = *(const float4*)&vb[(size_t)(n0 + n) * D_ + k4];
            *(float4*)&KVs[n * 68 + k4] = v;   // V tile row-major [n][d]
        }
        __syncthreads();
#pragma unroll
        for (int k = 0; k < 64; k++) {
            float a0 = Ss[(2 * ty) * SSTR + n0 + k];
            float a1 = Ss[(2 * ty + 1) * SSTR + n0 + k];
            float4 b = *(const float4*)&KVs[k * 68 + 4 * tx];
            o0[0] += a0 * b.x; o0[1] += a0 * b.y; o0[2] += a0 * b.z; o0[3] += a0 * b.w;
            o1[0] += a1 * b.x; o1[1] += a1 * b.y; o1[2] += a1 * b.z; o1[3] += a1 * b.w;
        }
        __syncthreads();
    }

    // Write O to g_o in [B*L, C] layout (c = h*64 + d)
    const int bb = bh / H_;
    const int h  = bh % H_;
    {
        int l0 = m0 + 2 * ty;
        *(float4*)&g_o[((size_t)(bb * L_ + l0) * C_) + h * D_ + 4 * tx] =
            make_float4(o0[0], o0[1], o0[2], o0[3]);
        *(float4*)&g_o[((size_t)(bb * L_ + l0 + 1) * C_) + h * D_ + 4 * tx] =
            make_float4(o1[0], o1[1], o1[2], o1[3]);
    }
}

// ---------------------------------------------------------------------------
// Kernel 3: output projection. out[m,f] = sum_c g_o[m,c]*w_proj[f,c] + b[f]
// ---------------------------------------------------------------------------
__global__ __launch_bounds__(256) void proj_gemm(const float* __restrict__ w,
                                                 const float* __restrict__ bias,
                                                 float* __restrict__ out)
{
    __shared__ float As[16 * 68];
    __shared__ float Bs[16 * 68];

    const int m0 = blockIdx.y * 64;
    const int n0 = blockIdx.x * 64;
    const int tid = threadIdx.x;
    const int ty = tid >> 4;
    const int tx = tid & 15;
    const int lm = tid >> 2;
    const int kq = (tid & 3) * 4;

    float acc[4][4];
#pragma unroll
    for (int i = 0; i < 4; i++)
#pragma unroll
        for (int j = 0; j < 4; j++) acc[i][j] = 0.f;

    for (int k0 = 0; k0 < C_; k0 += 16) {
        float4 av = *(const float4*)&g_o[(size_t)(m0 + lm) * C_ + k0 + kq];
        float4 bv = *(const float4*)&w[(size_t)(n0 + lm) * C_ + k0 + kq];
        As[(kq + 0) * 68 + lm] = av.x;
        As[(kq + 1) * 68 + lm] = av.y;
        As[(kq + 2) * 68 + lm] = av.z;
        As[(kq + 3) * 68 + lm] = av.w;
        Bs[(kq + 0) * 68 + lm] = bv.x;
        Bs[(kq + 1) * 68 + lm] = bv.y;
        Bs[(kq + 2) * 68 + lm] = bv.z;
        Bs[(kq + 3) * 68 + lm] = bv.w;
        __syncthreads();
#pragma unroll
        for (int k = 0; k < 16; k++) {
            float4 a = *(const float4*)&As[k * 68 + 4 * ty];
            float4 b = *(const float4*)&Bs[k * 68 + 4 * tx];
            acc[0][0] += a.x * b.x; acc[0][1] += a.x * b.y; acc[0][2] += a.x * b.z; acc[0][3] += a.x * b.w;
            acc[1][0] += a.y * b.x; acc[1][1] += a.y * b.y; acc[1][2] += a.y * b.z; acc[1][3] += a.y * b.w;
            acc[2][0] += a.z * b.x; acc[2][1] += a.z * b.y; acc[2][2] += a.z * b.z; acc[2][3] += a.z * b.w;
            acc[3][0] += a.w * b.x; acc[3][1] += a.w * b.y; acc[3][2] += a.w * b.z; acc[3][3] += a.w * b.w;
        }
        __syncthreads();
    }

    float4 bv = *(const float4*)&bias[n0 + 4 * tx];
#pragma unroll
    for (int i = 0; i < 4; i++) {
        int m = m0 + 4 * ty + i;
        float4 v = make_float4(acc[i][0] + bv.x, acc[i][1] + bv.y,
                               acc[i][2] + bv.z, acc[i][3] + bv.w);
        *(float4*)&out[(size_t)m * C_ + n0 + 4 * tx] = v;
    }
}

// ---------------------------------------------------------------------------
extern "C" void kernel_launch(void* const* d_in, const int* in_sizes, int n_in,
                              void* d_out, int out_size)
{
    const float* x      = (const float*)d_in[0];
    const float* w_qkv  = (const float*)d_in[1];
    const float* w_proj = (const float*)d_in[2];
    const float* b_proj = (const float*)d_in[3];

    float* out  = (float*)d_out;                       // tuple elem 0: [B,L,C]
    float* attn = out + (size_t)M_ * C_;               // tuple elem 1: [B,H,L,L]

    // 1. QKV projection -> g_q/g_k/g_v
    qkv_gemm<<<dim3(NQKV_ / 64, M_ / 64), 256>>>(x, w_qkv);

    // 2. Fused attention (scores + softmax + attn write + PV)
    const int smem_bytes = (32 * 68 + 64 * 68 + 32 * SSTR) * (int)sizeof(float);
    cudaFuncSetAttribute(attn_kernel, cudaFuncAttributeMaxDynamicSharedMemorySize,
                         smem_bytes);
    attn_kernel<<<dim3(L_ / 32, B_ * H_), 256, smem_bytes>>>(attn);

    // 3. Output projection + bias
    proj_gemm<<<dim3(C_ / 64, M_ / 64), 256>>>(w_proj, b_proj, out);
}

// round 3
// speedup vs baseline: 2.5235x; 2.5235x over previous
#include <cuda_runtime.h>

// Problem constants
#define B_ 4
#define L_ 1024
#define C_ 768
#define H_ 12
#define D_ 64
#define M_ (B_ * L_)      // 4096
#define NQKV_ (3 * C_)    // 2304

// Scratch (device globals; no allocation allowed)
__device__ float g_q[B_ * H_ * L_ * D_];   // [B,H,L,D]
__device__ float g_k[B_ * H_ * L_ * D_];
__device__ float g_v[B_ * H_ * L_ * D_];
__device__ float g_o[M_ * C_];             // attention output, [B*L, C]

// ---- TF32 helpers -----------------------------------------------------
__device__ __forceinline__ unsigned f2t(float f) {
    unsigned u;
    asm("cvt.rna.tf32.f32 %0, %1;" : "=r"(u) : "f"(f));
    return u;
}
__device__ __forceinline__ float f2tf(float f) { return __uint_as_float(f2t(f)); }

// mma.m16n8k8 row.col f32 += tf32*tf32
__device__ __forceinline__ void mma8(float* c, unsigned a0, unsigned a1,
                                     unsigned a2, unsigned a3,
                                     unsigned b0, unsigned b1) {
    asm volatile(
        "mma.sync.aligned.m16n8k8.row.col.f32.tf32.tf32.f32 "
        "{%0,%1,%2,%3},{%4,%5,%6,%7},{%8,%9},{%0,%1,%2,%3};"
        : "+f"(c[0]), "+f"(c[1]), "+f"(c[2]), "+f"(c[3])
        : "r"(a0), "r"(a1), "r"(a2), "r"(a3), "r"(b0), "r"(b1));
}

// ---------------------------------------------------------------------------
// Tensor-core NT GEMM, tile 128x128, BK=32, 256 threads (8 warps, 4x2).
// C[m,n] = sum_k A[m,k] * W[n,k]. K = 768 fixed.
// MODE 0: A = x (kernel arg); QKV epilogue -> g_q/g_k/g_v in [B,H,L,D]
// MODE 1: A = g_o (device global, referenced IN KERNEL); bias + store to out
// ---------------------------------------------------------------------------
template <int MODE>
__global__ __launch_bounds__(256, 2) void gemm_tc(const float* __restrict__ Ain,
                                                  const float* __restrict__ W,
                                                  const float* __restrict__ bias,
                                                  float* __restrict__ out)
{
    const float* A = (MODE == 0) ? Ain : (const float*)g_o;

    __shared__ float As[128 * 36];   // [m][k], stride 36 -> conflict-free frags
    __shared__ float Bs[128 * 36];   // [n][k]
    const unsigned* Au = (const unsigned*)As;
    const unsigned* Bu = (const unsigned*)Bs;

    const int tid = threadIdx.x;
    const int m0 = blockIdx.y * 128;
    const int n0 = blockIdx.x * 128;
    const int lrow = tid >> 3;        // 0..31
    const int lc4  = (tid & 7) * 4;   // 0..28

    const int warp = tid >> 5;
    const int lane = tid & 31;
    const int wm = warp >> 1;         // 0..3
    const int wn = warp & 1;          // 0..1
    const int mb = wm * 32;
    const int nb = wn * 64;
    const int gr = lane >> 2;         // 0..7
    const int tc = lane & 3;          // 0..3

    float acc[2][8][4];
#pragma unroll
    for (int mt = 0; mt < 2; mt++)
#pragma unroll
        for (int nt = 0; nt < 8; nt++)
#pragma unroll
            for (int i = 0; i < 4; i++) acc[mt][nt][i] = 0.f;

    for (int k0 = 0; k0 < 768; k0 += 32) {
#pragma unroll
        for (int p = 0; p < 4; p++) {
            int r = p * 32 + lrow;
            float4 va = *(const float4*)&A[(size_t)(m0 + r) * 768 + k0 + lc4];
            float4 vb = *(const float4*)&W[(size_t)(n0 + r) * 768 + k0 + lc4];
            *(float4*)&As[r * 36 + lc4] =
                make_float4(f2tf(va.x), f2tf(va.y), f2tf(va.z), f2tf(va.w));
            *(float4*)&Bs[r * 36 + lc4] =
                make_float4(f2tf(vb.x), f2tf(vb.y), f2tf(vb.z), f2tf(vb.w));
        }
        __syncthreads();

#pragma unroll
        for (int ks = 0; ks < 4; ks++) {
            unsigned a[2][4];
#pragma unroll
            for (int mt = 0; mt < 2; mt++) {
                int m = mb + mt * 16 + gr;
                a[mt][0] = Au[m * 36 + ks * 8 + tc];
                a[mt][1] = Au[(m + 8) * 36 + ks * 8 + tc];
                a[mt][2] = Au[m * 36 + ks * 8 + tc + 4];
                a[mt][3] = Au[(m + 8) * 36 + ks * 8 + tc + 4];
            }
#pragma unroll
            for (int nt = 0; nt < 8; nt++) {
                int n = nb + nt * 8 + gr;
                unsigned b0 = Bu[n * 36 + ks * 8 + tc];
                unsigned b1 = Bu[n * 36 + ks * 8 + tc + 4];
                mma8(acc[0][nt], a[0][0], a[0][1], a[0][2], a[0][3], b0, b1);
                mma8(acc[1][nt], a[1][0], a[1][1], a[1][2], a[1][3], b0, b1);
            }
        }
        __syncthreads();
    }

    // Epilogue
#pragma unroll
    for (int mt = 0; mt < 2; mt++) {
        int mg = m0 + mb + mt * 16 + gr;
#pragma unroll
        for (int nt = 0; nt < 8; nt++) {
            int f = n0 + nb + nt * 8 + tc * 2;
            if (MODE == 0) {
                int t = f / 768;
                int fr = f - t * 768;
                int h = fr >> 6;
                int d = fr & 63;
                int bb = mg >> 10;
                int l = mg & 1023;
                float* dst = (t == 0) ? g_q : (t == 1) ? g_k : g_v;
                size_t base = ((size_t)(bb * H_ + h) * L_ + l) * D_ + d;
                *(float2*)&dst[base] = make_float2(acc[mt][nt][0], acc[mt][nt][1]);
                *(float2*)&dst[base + 8 * D_] = make_float2(acc[mt][nt][2], acc[mt][nt][3]);
            } else {
                float2 bv = *(const float2*)&bias[f];
                size_t base = (size_t)mg * 768 + f;
                *(float2*)&out[base] =
                    make_float2(acc[mt][nt][0] + bv.x, acc[mt][nt][1] + bv.y);
                *(float2*)&out[base + (size_t)8 * 768] =
                    make_float2(acc[mt][nt][2] + bv.x, acc[mt][nt][3] + bv.y);
            }
        }
    }
}

// ---------------------------------------------------------------------------
// Fused attention per (b,h), 32 query rows per block, tensor-core QK^T + PV.
// Full 32x1024 score strip in smem; attn_score written to HBM exactly once.
// ---------------------------------------------------------------------------
#define QSTR 68
#define KSTR 72
#define SSTR2 1036

__global__ __launch_bounds__(256) void attn_tc(float* __restrict__ attn_out)
{
    extern __shared__ float sm[];
    float* Qs = sm;                          // 32 * 68
    float* Ks = sm + 32 * QSTR;              // 128 * 72 (K tiles, then V tiles)
    float* Ss = sm + 32 * QSTR + 128 * KSTR; // 32 * 1036
    const unsigned* Qu = (const unsigned*)Qs;
    const unsigned* Ku = (const unsigned*)Ks;
    const unsigned* Su = (const unsigned*)Ss;

    const int bh = blockIdx.y;
    const int m0 = blockIdx.x * 32;
    const int tid = threadIdx.x;
    const int warp = tid >> 5;
    const int lane = tid & 31;
    const int gr = lane >> 2;
    const int tc = lane & 3;

    const size_t head_base = (size_t)bh * L_ * D_;
    const float* qb = g_q + head_base;
    const float* kb = g_k + head_base;
    const float* vb = g_v + head_base;
    const float scale = 0.125f;

    // Load Q tile [32][64] (tf32-rounded)
#pragma unroll
    for (int p = 0; p < 2; p++) {
        int idx = p * 256 + tid;
        int r = idx >> 4;
        int c4 = (idx & 15) * 4;
        float4 v = *(const float4*)&qb[(size_t)(m0 + r) * D_ + c4];
        *(float4*)&Qs[r * QSTR + c4] =
            make_float4(f2tf(v.x), f2tf(v.y), f2tf(v.z), f2tf(v.w));
    }

    // ---- Phase A: S = scale * Q K^T ----
    for (int n0 = 0; n0 < L_; n0 += 128) {
#pragma unroll
        for (int p = 0; p < 8; p++) {
            int idx = p * 256 + tid;
            int r = idx >> 4;
            int c4 = (idx & 15) * 4;
            float4 v = *(const float4*)&kb[(size_t)(n0 + r) * D_ + c4];
            *(float4*)&Ks[r * KSTR + c4] =
                make_float4(f2tf(v.x), f2tf(v.y), f2tf(v.z), f2tf(v.w));
        }
        __syncthreads();

        float acc[2][2][4];
#pragma unroll
        for (int mt = 0; mt < 2; mt++)
#pragma unroll
            for (int nt = 0; nt < 2; nt++)
#pragma unroll
                for (int i = 0; i < 4; i++) acc[mt][nt][i] = 0.f;

#pragma unroll
        for (int ks = 0; ks < 8; ks++) {
            unsigned a[2][4];
#pragma unroll
            for (int mt = 0; mt < 2; mt++) {
                int m = mt * 16 + gr;
                a[mt][0] = Qu[m * QSTR + ks * 8 + tc];
                a[mt][1] = Qu[(m + 8) * QSTR + ks * 8 + tc];
                a[mt][2] = Qu[m * QSTR + ks * 8 + tc + 4];
                a[mt][3] = Qu[(m + 8) * QSTR + ks * 8 + tc + 4];
            }
#pragma unroll
            for (int nt = 0; nt < 2; nt++) {
                int n = warp * 16 + nt * 8 + gr;
                unsigned b0 = Ku[n * KSTR + ks * 8 + tc];
                unsigned b1 = Ku[n * KSTR + ks * 8 + tc + 4];
                mma8(acc[0][nt], a[0][0], a[0][1], a[0][2], a[0][3], b0, b1);
                mma8(acc[1][nt], a[1][0], a[1][1], a[1][2], a[1][3], b0, b1);
            }
        }

#pragma unroll
        for (int mt = 0; mt < 2; mt++)
#pragma unroll
            for (int nt = 0; nt < 2; nt++) {
                int r = mt * 16 + gr;
                int col = n0 + warp * 16 + nt * 8 + tc * 2;
                *(float2*)&Ss[r * SSTR2 + col] =
                    make_float2(acc[mt][nt][0] * scale, acc[mt][nt][1] * scale);
                *(float2*)&Ss[(r + 8) * SSTR2 + col] =
                    make_float2(acc[mt][nt][2] * scale, acc[mt][nt][3] * scale);
            }
        __syncthreads();
    }

    // ---- Phase B: softmax (warp w handles rows 4w..4w+3) ----
    float* attnb = attn_out + (size_t)bh * L_ * L_;
    for (int rr = 0; rr < 4; rr++) {
        int row = warp * 4 + rr;
        float* srow = &Ss[row * SSTR2];
        float pv[32];
        float mx = -1e30f;
#pragma unroll
        for (int j = 0; j < 32; j++) {
            pv[j] = srow[lane + 32 * j];
            mx = fmaxf(mx, pv[j]);
        }
#pragma unroll
        for (int o = 16; o > 0; o >>= 1)
            mx = fmaxf(mx, __shfl_xor_sync(0xffffffffu, mx, o));
        float sum = 0.f;
#pragma unroll
        for (int j = 0; j < 32; j++) {
            pv[j] = __expf(pv[j] - mx);
            sum += pv[j];
        }
#pragma unroll
        for (int o = 16; o > 0; o >>= 1)
            sum += __shfl_xor_sync(0xffffffffu, sum, o);
        float inv = 1.0f / sum;
        float* grow = attnb + (size_t)(m0 + row) * L_;
#pragma unroll
        for (int j = 0; j < 32; j++) {
            float p = pv[j] * inv;
            srow[lane + 32 * j] = f2tf(p);   // tf32-rounded copy for PV
            grow[lane + 32 * j] = p;         // full-precision attn_score output
        }
    }
    __syncthreads();

    // ---- Phase C: O = P V ----
    float oacc[2][4];
#pragma unroll
    for (int mt = 0; mt < 2; mt++)
#pragma unroll
        for (int i = 0; i < 4; i++) oacc[mt][i] = 0.f;

    for (int k0 = 0; k0 < L_; k0 += 128) {
#pragma unroll
        for (int p = 0; p < 8; p++) {
            int idx = p * 256 + tid;
            int r = idx >> 4;
            int c4 = (idx & 15) * 4;
            float4 v = *(const float4*)&vb[(size_t)(k0 + r) * D_ + c4];
            *(float4*)&Ks[r * KSTR + c4] =
                make_float4(f2tf(v.x), f2tf(v.y), f2tf(v.z), f2tf(v.w));
        }
        __syncthreads();

#pragma unroll
        for (int ks = 0; ks < 16; ks++) {
            unsigned a[2][4];
#pragma unroll
            for (int mt = 0; mt < 2; mt++) {
                int m = mt * 16 + gr;
                int kk = k0 + ks * 8 + tc;
                a[mt][0] = Su[m * SSTR2 + kk];
                a[mt][1] = Su[(m + 8) * SSTR2 + kk];
                a[mt][2] = Su[m * SSTR2 + kk + 4];
                a[mt][3] = Su[(m + 8) * SSTR2 + kk + 4];
            }
            int n = warp * 8 + gr;
            unsigned b0 = Ku[(ks * 8 + tc) * KSTR + n];
            unsigned b1 = Ku[(ks * 8 + tc + 4) * KSTR + n];
            mma8(oacc[0], a[0][0], a[0][1], a[0][2], a[0][3], b0, b1);
            mma8(oacc[1], a[1][0], a[1][1], a[1][2], a[1][3], b0, b1);
        }
        __syncthreads();
    }

    // Write O to g_o [B*L, C] (c = h*64 + d)
    const int bb = bh / H_;
    const int h = bh % H_;
#pragma unroll
    for (int mt = 0; mt < 2; mt++) {
        int rg = m0 + mt * 16 + gr;
        int d = warp * 8 + tc * 2;
        size_t addr = ((size_t)(bb * L_ + rg)) * C_ + h * D_ + d;
        *(float2*)&g_o[addr] = make_float2(oacc[mt][0], oacc[mt][1]);
        *(float2*)&g_o[addr + (size_t)8 * C_] = make_float2(oacc[mt][2], oacc[mt][3]);
    }
}

// ---------------------------------------------------------------------------
extern "C" void kernel_launch(void* const* d_in, const int* in_sizes, int n_in,
                              void* d_out, int out_size)
{
    const float* x      = (const float*)d_in[0];
    const float* w_qkv  = (const float*)d_in[1];
    const float* w_proj = (const float*)d_in[2];
    const float* b_proj = (const float*)d_in[3];

    float* out  = (float*)d_out;              // [B,L,C]
    float* attn = out + (size_t)M_ * C_;      // [B,H,L,L]

    // 1. QKV projection (tensor core)
    gemm_tc<0><<<dim3(NQKV_ / 128, M_ / 128), 256>>>(x, w_qkv, nullptr, nullptr);

    // 2. Fused attention (TC scores + softmax + attn write + TC PV)
    const int smem_bytes = (32 * QSTR + 128 * KSTR + 32 * SSTR2) * (int)sizeof(float);
    static int attr_set = 0;
    if (!attr_set) {
        cudaFuncSetAttribute(attn_tc, cudaFuncAttributeMaxDynamicSharedMemorySize,
                             smem_bytes);
        attr_set = 1;
    }
    attn_tc<<<dim3(L_ / 32, B_ * H_), 256, smem_bytes>>>(attn);

    // 3. Output projection + bias (tensor core). A operand (g_o) is read
    // inside the kernel — device globals must not be passed from host code.
    gemm_tc<1><<<dim3(C_ / 128, M_ / 128), 256>>>(nullptr, w_proj, b_proj, out);
}

// round 5
// speedup vs baseline: 3.0735x; 1.2180x over previous
#include <cuda_runtime.h>

// Problem constants
#define B_ 4
#define L_ 1024
#define C_ 768
#define H_ 12
#define D_ 64
#define M_ (B_ * L_)      // 4096
#define NQKV_ (3 * C_)    // 2304

// Scratch (device globals; no allocation allowed)
__device__ float g_q[B_ * H_ * L_ * D_];   // [B,H,L,D], tf32-rounded, q pre-scaled
__device__ float g_k[B_ * H_ * L_ * D_];
__device__ float g_v[B_ * H_ * L_ * D_];
__device__ float g_o[M_ * C_];             // attention output, tf32-rounded
__device__ float g_x[M_ * C_];             // tf32-rounded x
__device__ float g_wqkv[NQKV_ * C_];       // tf32-rounded w_qkv
__device__ float g_wproj[C_ * C_];         // tf32-rounded w_proj

// ---- helpers -----------------------------------------------------------
__device__ __forceinline__ float f2tf(float f) {
    unsigned u;
    asm("cvt.rna.tf32.f32 %0, %1;" : "=r"(u) : "f"(f));
    return __uint_as_float(u);
}
__device__ __forceinline__ void mma8(float* c, unsigned a0, unsigned a1,
                                     unsigned a2, unsigned a3,
                                     unsigned b0, unsigned b1) {
    asm volatile(
        "mma.sync.aligned.m16n8k8.row.col.f32.tf32.tf32.f32 "
        "{%0,%1,%2,%3},{%4,%5,%6,%7},{%8,%9},{%0,%1,%2,%3};"
        : "+f"(c[0]), "+f"(c[1]), "+f"(c[2]), "+f"(c[3])
        : "r"(a0), "r"(a1), "r"(a2), "r"(a3), "r"(b0), "r"(b1));
}
__device__ __forceinline__ void cpa16(void* s, const void* g) {
    unsigned sa = (unsigned)__cvta_generic_to_shared(s);
    asm volatile("cp.async.cg.shared.global [%0], [%1], 16;" :: "r"(sa), "l"(g));
}
__device__ __forceinline__ void cp_commit() {
    asm volatile("cp.async.commit_group;" ::: "memory");
}
__device__ __forceinline__ void cp_wait1() {
    asm volatile("cp.async.wait_group 1;" ::: "memory");
}
__device__ __forceinline__ void cp_wait0() {
    asm volatile("cp.async.wait_group 0;" ::: "memory");
}

// ---------------------------------------------------------------------------
// Kernel 0: pre-round x, w_qkv, w_proj to tf32 (float4 elementwise).
// ---------------------------------------------------------------------------
#define NX4  (M_ * C_ / 4)       // 786432
#define NWQ4 (NQKV_ * C_ / 4)    // 442368
#define NWP4 (C_ * C_ / 4)       // 147456
__global__ __launch_bounds__(256) void round_tf32(const float* __restrict__ x,
                                                  const float* __restrict__ wq,
                                                  const float* __restrict__ wp)
{
    int i = blockIdx.x * 256 + threadIdx.x;
    const float4* src;
    float4* dst;
    int j;
    if (i < NX4)                  { src = (const float4*)x;  dst = (float4*)g_x;     j = i; }
    else if (i < NX4 + NWQ4)      { src = (const float4*)wq; dst = (float4*)g_wqkv;  j = i - NX4; }
    else                          { src = (const float4*)wp; dst = (float4*)g_wproj; j = i - NX4 - NWQ4; }
    float4 v = src[j];
    dst[j] = make_float4(f2tf(v.x), f2tf(v.y), f2tf(v.z), f2tf(v.w));
}

// ---------------------------------------------------------------------------
// Tensor-core NT GEMM, 128x128 tile, BK=32, 256 threads, cp.async 2-stage.
// MODE 0: A=g_x, W=g_wqkv -> scatter to g_q/g_k/g_v (rounded; q scaled 0.125)
// MODE 1: A=g_o, W=g_wproj -> out + bias (full fp32 store)
// ---------------------------------------------------------------------------
#define GST 4608   // 128*36 floats per stage

// stage loader as a real function: args evaluated in caller scope (the R4
// macro version shadowed the caller's loop variable -> garbage addresses).
__device__ __forceinline__ void gload(float* as_dst, float* bs_dst,
                                      const float* a_src, const float* w_src,
                                      int tid)
{
#pragma unroll
    for (int u = 0; u < 4; u++) {
        int c = u * 256 + tid;
        int row = c >> 3, off = (c & 7) * 4;
        cpa16(&as_dst[row * 36 + off], &a_src[(size_t)row * 768 + off]);
        cpa16(&bs_dst[row * 36 + off], &w_src[(size_t)row * 768 + off]);
    }
}

template <int MODE>
__global__ __launch_bounds__(256, 2) void gemm_tc(const float* __restrict__ bias,
                                                  float* __restrict__ out)
{
    extern __shared__ float smg[];
    float* As = smg;               // [2][128*36]
    float* Bs = smg + 2 * GST;     // [2][128*36]

    const float* A = (MODE == 0) ? g_x : g_o;
    const float* W = (MODE == 0) ? g_wqkv : g_wproj;

    const int tid = threadIdx.x;
    const int m0 = blockIdx.y * 128;
    const int n0 = blockIdx.x * 128;

    const int warp = tid >> 5;
    const int lane = tid & 31;
    const int wm = warp >> 1;
    const int wn = warp & 1;
    const int mb = wm * 32;
    const int nb = wn * 64;
    const int gr = lane >> 2;
    const int tc = lane & 3;

    const float* Abase = A + (size_t)m0 * 768;
    const float* Wbase = W + (size_t)n0 * 768;

    float acc[2][8][4];
#pragma unroll
    for (int mt = 0; mt < 2; mt++)
#pragma unroll
        for (int nt = 0; nt < 8; nt++)
#pragma unroll
            for (int i = 0; i < 4; i++) acc[mt][nt][i] = 0.f;

    gload(As, Bs, Abase, Wbase, tid);
    cp_commit();

    for (int kt = 0; kt < 24; kt++) {
        if (kt + 1 < 24) {
            int st = (kt + 1) & 1;
            int k0 = (kt + 1) * 32;
            gload(As + st * GST, Bs + st * GST, Abase + k0, Wbase + k0, tid);
            cp_commit();
            cp_wait1();
        } else {
            cp_wait0();
        }
        __syncthreads();

        const unsigned* Au = (const unsigned*)(As + (kt & 1) * GST);
        const unsigned* Bu = (const unsigned*)(Bs + (kt & 1) * GST);
#pragma unroll
        for (int ks = 0; ks < 4; ks++) {
            unsigned a[2][4];
#pragma unroll
            for (int mt = 0; mt < 2; mt++) {
                int m = mb + mt * 16 + gr;
                a[mt][0] = Au[m * 36 + ks * 8 + tc];
                a[mt][1] = Au[(m + 8) * 36 + ks * 8 + tc];
                a[mt][2] = Au[m * 36 + ks * 8 + tc + 4];
                a[mt][3] = Au[(m + 8) * 36 + ks * 8 + tc + 4];
            }
#pragma unroll
            for (int nt = 0; nt < 8; nt++) {
                int n = nb + nt * 8 + gr;
                unsigned b0 = Bu[n * 36 + ks * 8 + tc];
                unsigned b1 = Bu[n * 36 + ks * 8 + tc + 4];
                mma8(acc[0][nt], a[0][0], a[0][1], a[0][2], a[0][3], b0, b1);
                mma8(acc[1][nt], a[1][0], a[1][1], a[1][2], a[1][3], b0, b1);
            }
        }
        __syncthreads();
    }

    // Epilogue
#pragma unroll
    for (int mt = 0; mt < 2; mt++) {
        int mg = m0 + mb + mt * 16 + gr;
#pragma unroll
        for (int nt = 0; nt < 8; nt++) {
            int f = n0 + nb + nt * 8 + tc * 2;
            if (MODE == 0) {
                int t = f / 768;
                int fr = f - t * 768;
                int h = fr >> 6;
                int d = fr & 63;
                int bb = mg >> 10;
                int l = mg & 1023;
                float s = (t == 0) ? 0.125f : 1.0f;   // fold 1/sqrt(D) into q
                float* dst = (t == 0) ? g_q : (t == 1) ? g_k : g_v;
                size_t base = ((size_t)(bb * H_ + h) * L_ + l) * D_ + d;
                *(float2*)&dst[base] =
                    make_float2(f2tf(acc[mt][nt][0] * s), f2tf(acc[mt][nt][1] * s));
                *(float2*)&dst[base + 8 * D_] =
                    make_float2(f2tf(acc[mt][nt][2] * s), f2tf(acc[mt][nt][3] * s));
            } else {
                float2 bv = *(const float2*)&bias[f];
                size_t base = (size_t)mg * 768 + f;
                *(float2*)&out[base] =
                    make_float2(acc[mt][nt][0] + bv.x, acc[mt][nt][1] + bv.y);
                *(float2*)&out[base + (size_t)8 * 768] =
                    make_float2(acc[mt][nt][2] + bv.x, acc[mt][nt][3] + bv.y);
            }
        }
    }
}

// ---------------------------------------------------------------------------
// Fused attention per (b,h): 512 threads (16 warps), 32 query rows per block.
// cp.async double-buffered K/V tiles; full 32x1024 score strip in smem;
// attn written to HBM exactly once.
// ---------------------------------------------------------------------------
#define QSTR 68
#define KSTR 76
#define KST  (128 * KSTR)   // per-stage floats
#define SSTR2 1036

// K/V tile loader (function, not macro: args evaluated in caller scope).
__device__ __forceinline__ void kvload(float* dst, const float* src, int tid)
{
#pragma unroll
    for (int u = 0; u < 4; u++) {
        int c = u * 512 + tid;
        int row = c >> 4, off = (c & 15) * 4;
        cpa16(&dst[row * KSTR + off], &src[(size_t)row * D_ + off]);
    }
}

__global__ __launch_bounds__(512) void attn_tc(float* __restrict__ attn_out)
{
    extern __shared__ float sm[];
    float* Qs = sm;                           // 32*68
    float* Ks = sm + 32 * QSTR;               // [2][128*76]
    float* Ss = sm + 32 * QSTR + 2 * KST;     // 32*1036
    const unsigned* Qu = (const unsigned*)Qs;
    const unsigned* Su = (const unsigned*)Ss;

    const int bh = blockIdx.y;
    const int m0 = blockIdx.x * 32;
    const int tid = threadIdx.x;
    const int warp = tid >> 5;
    const int lane = tid & 31;
    const int gr = lane >> 2;
    const int tc = lane & 3;

    const size_t head_base = (size_t)bh * L_ * D_;
    const float* qb = g_q + head_base;
    const float* kb = g_k + head_base;
    const float* vb = g_v + head_base;

    // Q tile [32][64]: 512 float4 chunks, 1 per thread (already tf32+scaled)
    {
        int r = tid >> 4, c4 = (tid & 15) * 4;
        *(float4*)&Qs[r * QSTR + c4] = *(const float4*)&qb[(size_t)(m0 + r) * D_ + c4];
    }

    // ---- Phase A: S = Q K^T (q pre-scaled). warp: mt=w&1, ncol=(w>>1)*16 ----
    kvload(Ks, kb, tid);
    cp_commit();
    const int mtA = warp & 1;
    const int nbA = (warp >> 1) * 16;

    for (int t = 0; t < 8; t++) {
        if (t + 1 < 8) {
            kvload(Ks + ((t + 1) & 1) * KST, kb + (size_t)(t + 1) * 128 * D_, tid);
            cp_commit();
            cp_wait1();
        } else {
            cp_wait0();
        }
        __syncthreads();

        const unsigned* Ku = (const unsigned*)(Ks + (t & 1) * KST);
        float acc[2][4];
#pragma unroll
        for (int nt = 0; nt < 2; nt++)
#pragma unroll
            for (int i = 0; i < 4; i++) acc[nt][i] = 0.f;

#pragma unroll
        for (int ks = 0; ks < 8; ks++) {
            int m = mtA * 16 + gr;
            unsigned a0 = Qu[m * QSTR + ks * 8 + tc];
            unsigned a1 = Qu[(m + 8) * QSTR + ks * 8 + tc];
            unsigned a2 = Qu[m * QSTR + ks * 8 + tc + 4];
            unsigned a3 = Qu[(m + 8) * QSTR + ks * 8 + tc + 4];
#pragma unroll
            for (int nt = 0; nt < 2; nt++) {
                int n = nbA + nt * 8 + gr;
                unsigned b0 = Ku[n * KSTR + ks * 8 + tc];
                unsigned b1 = Ku[n * KSTR + ks * 8 + tc + 4];
                mma8(acc[nt], a0, a1, a2, a3, b0, b1);
            }
        }
#pragma unroll
        for (int nt = 0; nt < 2; nt++) {
            int r = mtA * 16 + gr;
            int col = t * 128 + nbA + nt * 8 + tc * 2;
            *(float2*)&Ss[r * SSTR2 + col] = make_float2(acc[nt][0], acc[nt][1]);
            *(float2*)&Ss[(r + 8) * SSTR2 + col] = make_float2(acc[nt][2], acc[nt][3]);
        }
        __syncthreads();
    }

    // Prefetch V tile 0 (overlaps with softmax; Ks buffers are free now)
    kvload(Ks, vb, tid);
    cp_commit();

    // ---- Phase B: softmax, warp handles rows 2w, 2w+1 ----
    float* attnb = attn_out + (size_t)bh * L_ * L_;
#pragma unroll
    for (int rr = 0; rr < 2; rr++) {
        int row = warp * 2 + rr;
        float* srow = &Ss[row * SSTR2];
        float pv[32];
        float mx = -1e30f;
#pragma unroll
        for (int j = 0; j < 32; j++) {
            pv[j] = srow[lane + 32 * j];
            mx = fmaxf(mx, pv[j]);
        }
#pragma unroll
        for (int o = 16; o > 0; o >>= 1)
            mx = fmaxf(mx, __shfl_xor_sync(0xffffffffu, mx, o));
        float sum = 0.f;
#pragma unroll
        for (int j = 0; j < 32; j++) {
            pv[j] = __expf(pv[j] - mx);
            sum += pv[j];
        }
#pragma unroll
        for (int o = 16; o > 0; o >>= 1)
            sum += __shfl_xor_sync(0xffffffffu, sum, o);
        float inv = 1.0f / sum;
        float* grow = attnb + (size_t)(m0 + row) * L_;
#pragma unroll
        for (int j = 0; j < 32; j++) {
            float p = pv[j] * inv;
            srow[lane + 32 * j] = f2tf(p);   // tf32 copy for PV
            grow[lane + 32 * j] = p;         // full-precision attn_score
        }
    }

    // ---- Phase C: O = P V. warp: mt=w>>3, nt=w&7 -> m16n8 output ----
    const int mtC = warp >> 3;
    const int nC = (warp & 7) * 8 + gr;
    float oacc[4] = {0.f, 0.f, 0.f, 0.f};

    for (int t = 0; t < 8; t++) {
        if (t + 1 < 8) {
            kvload(Ks + ((t + 1) & 1) * KST, vb + (size_t)(t + 1) * 128 * D_, tid);
            cp_commit();
            cp_wait1();
        } else {
            cp_wait0();
        }
        __syncthreads();

        const unsigned* Vu = (const unsigned*)(Ks + (t & 1) * KST);
        const int k0 = t * 128;
#pragma unroll
        for (int ks = 0; ks < 16; ks++) {
            int m = mtC * 16 + gr;
            int kk = k0 + ks * 8 + tc;
            unsigned a0 = Su[m * SSTR2 + kk];
            unsigned a1 = Su[(m + 8) * SSTR2 + kk];
            unsigned a2 = Su[m * SSTR2 + kk + 4];
            unsigned a3 = Su[(m + 8) * SSTR2 + kk + 4];
            unsigned b0 = Vu[(ks * 8 + tc) * KSTR + nC];
            unsigned b1 = Vu[(ks * 8 + tc + 4) * KSTR + nC];
            mma8(oacc, a0, a1, a2, a3, b0, b1);
        }
        __syncthreads();
    }

    // Write O to g_o [B*L, C] (c = h*64 + d), tf32-rounded for proj GEMM
    const int bb = bh / H_;
    const int h = bh % H_;
    {
        int rg = m0 + mtC * 16 + gr;
        int d = (warp & 7) * 8 + tc * 2;
        size_t addr = ((size_t)(bb * L_ + rg)) * C_ + h * D_ + d;
        *(float2*)&g_o[addr] = make_float2(f2tf(oacc[0]), f2tf(oacc[1]));
        *(float2*)&g_o[addr + (size_t)8 * C_] = make_float2(f2tf(oacc[2]), f2tf(oacc[3]));
    }
}

// ---------------------------------------------------------------------------
extern "C" void kernel_launch(void* const* d_in, const int* in_sizes, int n_in,
                              void* d_out, int out_size)
{
    const float* x      = (const float*)d_in[0];
    const float* w_qkv  = (const float*)d_in[1];
    const float* w_proj = (const float*)d_in[2];
    const float* b_proj = (const float*)d_in[3];

    float* out  = (float*)d_out;              // [B,L,C]
    float* attn = out + (size_t)M_ * C_;      // [B,H,L,L]

    const int gemm_smem = 4 * GST * (int)sizeof(float);                 // 73728
    const int attn_smem = (32 * QSTR + 2 * KST + 32 * SSTR2) * (int)sizeof(float);

    cudaFuncSetAttribute(gemm_tc<0>, cudaFuncAttributeMaxDynamicSharedMemorySize, gemm_smem);
    cudaFuncSetAttribute(gemm_tc<1>, cudaFuncAttributeMaxDynamicSharedMemorySize, gemm_smem);
    cudaFuncSetAttribute(attn_tc, cudaFuncAttributeMaxDynamicSharedMemorySize, attn_smem);

    // 0. Pre-round inputs to tf32
    round_tf32<<<(NX4 + NWQ4 + NWP4) / 256, 256>>>(x, w_qkv, w_proj);

    // 1. QKV projection
    gemm_tc<0><<<dim3(NQKV_ / 128, M_ / 128), 256, gemm_smem>>>(nullptr, nullptr);

    // 2. Fused attention
    attn_tc<<<dim3(L_ / 32, B_ * H_), 512, attn_smem>>>(attn);

    // 3. Output projection + bias
    gemm_tc<1><<<dim3(C_ / 128, M_ / 128), 256, gemm_smem>>>(b_proj, out);
}

// round 6
// speedup vs baseline: 3.7921x; 1.2338x over previous
#include <cuda_runtime.h>

// Problem constants
#define B_ 4
#define L_ 1024
#define C_ 768
#define H_ 12
#define D_ 64
#define M_ (B_ * L_)      // 4096
#define NQKV_ (3 * C_)    // 2304

// Scratch (device globals; no allocation allowed)
__device__ float g_q[B_ * H_ * L_ * D_];   // [B,H,L,D], tf32-rounded, q pre-scaled
__device__ float g_k[B_ * H_ * L_ * D_];   // [B,H,L,D], tf32-rounded
__device__ float g_vt[B_ * H_ * D_ * L_];  // [B,H,D,L]  V TRANSPOSED, tf32-rounded
__device__ float g_o[M_ * C_];             // attention output, tf32-rounded
__device__ float g_x[M_ * C_];             // tf32-rounded x
__device__ float g_wqkv[NQKV_ * C_];       // tf32-rounded w_qkv
__device__ float g_wproj[C_ * C_];         // tf32-rounded w_proj

// ---- helpers -----------------------------------------------------------
__device__ __forceinline__ unsigned f2t(float f) {
    unsigned u;
    asm("cvt.rna.tf32.f32 %0, %1;" : "=r"(u) : "f"(f));
    return u;
}
__device__ __forceinline__ float f2tf(float f) { return __uint_as_float(f2t(f)); }

__device__ __forceinline__ void mma8(float* c, unsigned a0, unsigned a1,
                                     unsigned a2, unsigned a3,
                                     unsigned b0, unsigned b1) {
    asm volatile(
        "mma.sync.aligned.m16n8k8.row.col.f32.tf32.tf32.f32 "
        "{%0,%1,%2,%3},{%4,%5,%6,%7},{%8,%9},{%0,%1,%2,%3};"
        : "+f"(c[0]), "+f"(c[1]), "+f"(c[2]), "+f"(c[3])
        : "r"(a0), "r"(a1), "r"(a2), "r"(a3), "r"(b0), "r"(b1));
}
__device__ __forceinline__ void cpa16(void* s, const void* g) {
    unsigned sa = (unsigned)__cvta_generic_to_shared(s);
    asm volatile("cp.async.cg.shared.global [%0], [%1], 16;" :: "r"(sa), "l"(g));
}
__device__ __forceinline__ void cp_commit() {
    asm volatile("cp.async.commit_group;" ::: "memory");
}
__device__ __forceinline__ void cp_wait1() {
    asm volatile("cp.async.wait_group 1;" ::: "memory");
}
__device__ __forceinline__ void cp_wait0() {
    asm volatile("cp.async.wait_group 0;" ::: "memory");
}

// ---------------------------------------------------------------------------
// Kernel 0: pre-round x, w_qkv, w_proj to tf32.
// ---------------------------------------------------------------------------
#define NX4  (M_ * C_ / 4)
#define NWQ4 (NQKV_ * C_ / 4)
#define NWP4 (C_ * C_ / 4)
__global__ __launch_bounds__(256) void round_tf32(const float* __restrict__ x,
                                                  const float* __restrict__ wq,
                                                  const float* __restrict__ wp)
{
    int i = blockIdx.x * 256 + threadIdx.x;
    const float4* src;
    float4* dst;
    int j;
    if (i < NX4)                  { src = (const float4*)x;  dst = (float4*)g_x;     j = i; }
    else if (i < NX4 + NWQ4)      { src = (const float4*)wq; dst = (float4*)g_wqkv;  j = i - NX4; }
    else                          { src = (const float4*)wp; dst = (float4*)g_wproj; j = i - NX4 - NWQ4; }
    float4 v = src[j];
    dst[j] = make_float4(f2tf(v.x), f2tf(v.y), f2tf(v.z), f2tf(v.w));
}

// ---------------------------------------------------------------------------
// Tensor-core NT GEMM, 128x128 tile, BK=32, 256 threads, cp.async 2-stage.
// MODE 0: A=g_x, W=g_wqkv -> q,k to [B,H,L,D]; v to g_vt [B,H,D,L]
// MODE 1: A=g_o, W=g_wproj -> out + bias (full fp32 store)
// ---------------------------------------------------------------------------
#define GST 4608   // 128*36 floats per stage

__device__ __forceinline__ void gload(float* as_dst, float* bs_dst,
                                      const float* a_src, const float* w_src,
                                      int tid)
{
#pragma unroll
    for (int u = 0; u < 4; u++) {
        int c = u * 256 + tid;
        int row = c >> 3, off = (c & 7) * 4;
        cpa16(&as_dst[row * 36 + off], &a_src[(size_t)row * 768 + off]);
        cpa16(&bs_dst[row * 36 + off], &w_src[(size_t)row * 768 + off]);
    }
}

template <int MODE>
__global__ __launch_bounds__(256, 2) void gemm_tc(const float* __restrict__ bias,
                                                  float* __restrict__ out)
{
    extern __shared__ float smg[];
    float* As = smg;
    float* Bs = smg + 2 * GST;

    const float* A = (MODE == 0) ? g_x : g_o;
    const float* W = (MODE == 0) ? g_wqkv : g_wproj;

    const int tid = threadIdx.x;
    const int m0 = blockIdx.y * 128;
    const int n0 = blockIdx.x * 128;

    const int warp = tid >> 5;
    const int lane = tid & 31;
    const int wm = warp >> 1;
    const int wn = warp & 1;
    const int mb = wm * 32;
    const int nb = wn * 64;
    const int gr = lane >> 2;
    const int tc = lane & 3;

    const float* Abase = A + (size_t)m0 * 768;
    const float* Wbase = W + (size_t)n0 * 768;

    float acc[2][8][4];
#pragma unroll
    for (int mt = 0; mt < 2; mt++)
#pragma unroll
        for (int nt = 0; nt < 8; nt++)
#pragma unroll
            for (int i = 0; i < 4; i++) acc[mt][nt][i] = 0.f;

    gload(As, Bs, Abase, Wbase, tid);
    cp_commit();

    for (int kt = 0; kt < 24; kt++) {
        if (kt + 1 < 24) {
            int st = (kt + 1) & 1;
            int k0 = (kt + 1) * 32;
            gload(As + st * GST, Bs + st * GST, Abase + k0, Wbase + k0, tid);
            cp_commit();
            cp_wait1();
        } else {
            cp_wait0();
        }
        __syncthreads();

        const unsigned* Au = (const unsigned*)(As + (kt & 1) * GST);
        const unsigned* Bu = (const unsigned*)(Bs + (kt & 1) * GST);
#pragma unroll
        for (int ks = 0; ks < 4; ks++) {
            unsigned a[2][4];
#pragma unroll
            for (int mt = 0; mt < 2; mt++) {
                int m = mb + mt * 16 + gr;
                a[mt][0] = Au[m * 36 + ks * 8 + tc];
                a[mt][1] = Au[(m + 8) * 36 + ks * 8 + tc];
                a[mt][2] = Au[m * 36 + ks * 8 + tc + 4];
                a[mt][3] = Au[(m + 8) * 36 + ks * 8 + tc + 4];
            }
#pragma unroll
            for (int nt = 0; nt < 8; nt++) {
                int n = nb + nt * 8 + gr;
                unsigned b0 = Bu[n * 36 + ks * 8 + tc];
                unsigned b1 = Bu[n * 36 + ks * 8 + tc + 4];
                mma8(acc[0][nt], a[0][0], a[0][1], a[0][2], a[0][3], b0, b1);
                mma8(acc[1][nt], a[1][0], a[1][1], a[1][2], a[1][3], b0, b1);
            }
        }
        __syncthreads();
    }

    // Epilogue
#pragma unroll
    for (int mt = 0; mt < 2; mt++) {
        int mg = m0 + mb + mt * 16 + gr;
#pragma unroll
        for (int nt = 0; nt < 8; nt++) {
            int f = n0 + nb + nt * 8 + tc * 2;
            if (MODE == 0) {
                int t = f / 768;
                int fr = f - t * 768;
                int h = fr >> 6;
                int d = fr & 63;
                int bb = mg >> 10;
                int l = mg & 1023;
                if (t == 2) {
                    // V: transposed store [B,H,D,L]
                    size_t vb = ((size_t)(bb * H_ + h) * D_ + d) * L_ + l;
                    g_vt[vb]            = f2tf(acc[mt][nt][0]);
                    g_vt[vb + L_]       = f2tf(acc[mt][nt][1]);
                    g_vt[vb + 8]        = f2tf(acc[mt][nt][2]);
                    g_vt[vb + L_ + 8]   = f2tf(acc[mt][nt][3]);
                } else {
                    float s = (t == 0) ? 0.125f : 1.0f;  // fold 1/sqrt(D) into q
                    float* dst = (t == 0) ? g_q : g_k;
                    size_t base = ((size_t)(bb * H_ + h) * L_ + l) * D_ + d;
                    *(float2*)&dst[base] =
                        make_float2(f2tf(acc[mt][nt][0] * s), f2tf(acc[mt][nt][1] * s));
                    *(float2*)&dst[base + 8 * D_] =
                        make_float2(f2tf(acc[mt][nt][2] * s), f2tf(acc[mt][nt][3] * s));
                }
            } else {
                float2 bv = *(const float2*)&bias[f];
                size_t base = (size_t)mg * 768 + f;
                *(float2*)&out[base] =
                    make_float2(acc[mt][nt][0] + bv.x, acc[mt][nt][1] + bv.y);
                *(float2*)&out[base + (size_t)8 * 768] =
                    make_float2(acc[mt][nt][2] + bv.x, acc[mt][nt][3] + bv.y);
            }
        }
    }
}

// ---------------------------------------------------------------------------
// Attention scores kernel: S = softmax(Q K^T) per (b,h), 32 q-rows per block,
// 512 threads. Scores live entirely in REGISTERS (64/thread); K double-buffered
// via cp.async; softmax via shfl + tiny smem exchange; single gmem attn write.
// ---------------------------------------------------------------------------
#define KSTR 76
#define KST  (128 * KSTR)

__device__ __forceinline__ void kvload(float* dst, const float* src, int tid)
{
#pragma unroll
    for (int u = 0; u < 4; u++) {
        int c = u * 512 + tid;
        int row = c >> 4, off = (c & 15) * 4;
        cpa16(&dst[row * KSTR + off], &src[(size_t)row * D_ + off]);
    }
}

__global__ __launch_bounds__(512) void attn_tc(float* __restrict__ attn_out)
{
    extern __shared__ float sm[];
    float* Ks    = sm;                // [2][128*76]
    float* sredm = sm + 2 * KST;      // [32][8] row-max partials
    float* sreds = sredm + 256;       // [32][8] row-sum partials

    const int bh = blockIdx.y;
    const int m0 = blockIdx.x * 32;
    const int tid = threadIdx.x;
    const int warp = tid >> 5;
    const int lane = tid & 31;
    const int gr = lane >> 2;
    const int tc = lane & 3;
    const int mtA = warp & 1;       // 16-row half
    const int cg  = warp >> 1;      // 0..7 column group (16 cols per K tile)

    const size_t head_base = (size_t)bh * L_ * D_;
    const float* qb = g_q + head_base;
    const float* kb = g_k + head_base;

    // Q fragments straight from gmem (L2-hot, loaded once; pre-scaled tf32)
    unsigned qa[8][4];
    {
        const float* r0 = qb + (size_t)(m0 + mtA * 16 + gr) * D_;
        const float* r1 = r0 + 8 * D_;
#pragma unroll
        for (int ks = 0; ks < 8; ks++) {
            qa[ks][0] = __float_as_uint(r0[ks * 8 + tc]);
            qa[ks][1] = __float_as_uint(r1[ks * 8 + tc]);
            qa[ks][2] = __float_as_uint(r0[ks * 8 + tc + 4]);
            qa[ks][3] = __float_as_uint(r1[ks * 8 + tc + 4]);
        }
    }

    float sc[8][2][4];   // [k-tile][nt][frag] — the full score strip slice
#pragma unroll
    for (int t = 0; t < 8; t++)
#pragma unroll
        for (int nt = 0; nt < 2; nt++)
#pragma unroll
            for (int i = 0; i < 4; i++) sc[t][nt][i] = 0.f;

    kvload(Ks, kb, tid);
    cp_commit();

    for (int t = 0; t < 8; t++) {
        if (t + 1 < 8) {
            kvload(Ks + ((t + 1) & 1) * KST, kb + (size_t)(t + 1) * 128 * D_, tid);
            cp_commit();
            cp_wait1();
        } else {
            cp_wait0();
        }
        __syncthreads();

        const unsigned* Ku = (const unsigned*)(Ks + (t & 1) * KST);
#pragma unroll
        for (int ks = 0; ks < 8; ks++) {
#pragma unroll
            for (int nt = 0; nt < 2; nt++) {
                int n = cg * 16 + nt * 8 + gr;
                unsigned b0 = Ku[n * KSTR + ks * 8 + tc];
                unsigned b1 = Ku[n * KSTR + ks * 8 + tc + 4];
                mma8(sc[t][nt], qa[ks][0], qa[ks][1], qa[ks][2], qa[ks][3], b0, b1);
            }
        }
        __syncthreads();
    }

    // ---- softmax over registers ----
    const int rA = mtA * 16 + gr;
    const int rB = rA + 8;

    float mxA = -1e30f, mxB = -1e30f;
#pragma unroll
    for (int t = 0; t < 8; t++)
#pragma unroll
        for (int nt = 0; nt < 2; nt++) {
            mxA = fmaxf(mxA, fmaxf(sc[t][nt][0], sc[t][nt][1]));
            mxB = fmaxf(mxB, fmaxf(sc[t][nt][2], sc[t][nt][3]));
        }
    mxA = fmaxf(mxA, __shfl_xor_sync(0xffffffffu, mxA, 1));
    mxA = fmaxf(mxA, __shfl_xor_sync(0xffffffffu, mxA, 2));
    mxB = fmaxf(mxB, __shfl_xor_sync(0xffffffffu, mxB, 1));
    mxB = fmaxf(mxB, __shfl_xor_sync(0xffffffffu, mxB, 2));
    if (tc == 0) {
        sredm[rA * 8 + cg] = mxA;
        sredm[rB * 8 + cg] = mxB;
    }
    __syncthreads();
    mxA = sredm[rA * 8];
    mxB = sredm[rB * 8];
#pragma unroll
    for (int j = 1; j < 8; j++) {
        mxA = fmaxf(mxA, sredm[rA * 8 + j]);
        mxB = fmaxf(mxB, sredm[rB * 8 + j]);
    }

    float sA = 0.f, sB = 0.f;
#pragma unroll
    for (int t = 0; t < 8; t++)
#pragma unroll
        for (int nt = 0; nt < 2; nt++) {
            sc[t][nt][0] = __expf(sc[t][nt][0] - mxA);
            sc[t][nt][1] = __expf(sc[t][nt][1] - mxA);
            sc[t][nt][2] = __expf(sc[t][nt][2] - mxB);
            sc[t][nt][3] = __expf(sc[t][nt][3] - mxB);
            sA += sc[t][nt][0] + sc[t][nt][1];
            sB += sc[t][nt][2] + sc[t][nt][3];
        }
    sA += __shfl_xor_sync(0xffffffffu, sA, 1);
    sA += __shfl_xor_sync(0xffffffffu, sA, 2);
    sB += __shfl_xor_sync(0xffffffffu, sB, 1);
    sB += __shfl_xor_sync(0xffffffffu, sB, 2);
    if (tc == 0) {
        sreds[rA * 8 + cg] = sA;
        sreds[rB * 8 + cg] = sB;
    }
    __syncthreads();
    sA = 0.f; sB = 0.f;
#pragma unroll
    for (int j = 0; j < 8; j++) {
        sA += sreds[rA * 8 + j];
        sB += sreds[rB * 8 + j];
    }
    const float invA = 1.0f / sA;
    const float invB = 1.0f / sB;

    // ---- write attn (fp32, exactly once) ----
    float* rowA = attn_out + (size_t)bh * L_ * L_ + (size_t)(m0 + rA) * L_;
    float* rowB = attn_out + (size_t)bh * L_ * L_ + (size_t)(m0 + rB) * L_;
#pragma unroll
    for (int t = 0; t < 8; t++)
#pragma unroll
        for (int nt = 0; nt < 2; nt++) {
            int col = t * 128 + cg * 16 + nt * 8 + tc * 2;
            *(float2*)&rowA[col] = make_float2(sc[t][nt][0] * invA, sc[t][nt][1] * invA);
            *(float2*)&rowB[col] = make_float2(sc[t][nt][2] * invB, sc[t][nt][3] * invB);
        }
}

// ---------------------------------------------------------------------------
// PV GEMM: O[b,h] = P[1024,1024] * V[1024,64]. A = attn (fp32 gmem, cvt.rna at
// fragment load), B = g_vt rows [d][l]. 128m x 64n tiles, 256 threads,
// cp.async 2-stage. Epilogue -> g_o [B*L, C], tf32-rounded.
// ---------------------------------------------------------------------------
#define PAST 4608   // 128*36
#define PBST 2304   // 64*36

__device__ __forceinline__ void pvload(float* as_dst, float* bs_dst,
                                       const float* a_src, const float* b_src,
                                       int tid)
{
#pragma unroll
    for (int u = 0; u < 4; u++) {
        int c = u * 256 + tid;
        int row = c >> 3, off = (c & 7) * 4;
        cpa16(&as_dst[row * 36 + off], &a_src[(size_t)row * 1024 + off]);
    }
#pragma unroll
    for (int u = 0; u < 2; u++) {
        int c = u * 256 + tid;
        int row = c >> 3, off = (c & 7) * 4;
        cpa16(&bs_dst[row * 36 + off], &b_src[(size_t)row * 1024 + off]);
    }
}

__global__ __launch_bounds__(256) void pv_tc(const float* __restrict__ attn)
{
    extern __shared__ float smp[];
    float* As = smp;                // [2][128*36]
    float* Bs = smp + 2 * PAST;     // [2][64*36]

    const int bh = blockIdx.y;
    const int m0 = blockIdx.x * 128;
    const int tid = threadIdx.x;
    const int warp = tid >> 5;
    const int lane = tid & 31;
    const int gr = lane >> 2;
    const int tc = lane & 3;
    const int wm = warp >> 1;   // 0..3
    const int wn = warp & 1;    // 0..1

    const float* Ab = attn + (size_t)bh * L_ * L_ + (size_t)m0 * 1024;
    const float* Bb = g_vt + (size_t)bh * D_ * L_;

    float acc[2][4][4];
#pragma unroll
    for (int mt = 0; mt < 2; mt++)
#pragma unroll
        for (int nt = 0; nt < 4; nt++)
#pragma unroll
            for (int i = 0; i < 4; i++) acc[mt][nt][i] = 0.f;

    pvload(As, Bs, Ab, Bb, tid);
    cp_commit();

    for (int kt = 0; kt < 32; kt++) {
        if (kt + 1 < 32) {
            int st = (kt + 1) & 1;
            int k0 = (kt + 1) * 32;
            pvload(As + st * PAST, Bs + st * PBST, Ab + k0, Bb + k0, tid);
            cp_commit();
            cp_wait1();
        } else {
            cp_wait0();
        }
        __syncthreads();

        const float* Af = As + (kt & 1) * PAST;
        const unsigned* Bu = (const unsigned*)(Bs + (kt & 1) * PBST);
#pragma unroll
        for (int ks = 0; ks < 4; ks++) {
            unsigned a[2][4];
#pragma unroll
            for (int mt = 0; mt < 2; mt++) {
                int m = wm * 32 + mt * 16 + gr;
                a[mt][0] = f2t(Af[m * 36 + ks * 8 + tc]);
                a[mt][1] = f2t(Af[(m + 8) * 36 + ks * 8 + tc]);
                a[mt][2] = f2t(Af[m * 36 + ks * 8 + tc + 4]);
                a[mt][3] = f2t(Af[(m + 8) * 36 + ks * 8 + tc + 4]);
            }
#pragma unroll
            for (int nt = 0; nt < 4; nt++) {
                int n = wn * 32 + nt * 8 + gr;
                unsigned b0 = Bu[n * 36 + ks * 8 + tc];
                unsigned b1 = Bu[n * 36 + ks * 8 + tc + 4];
                mma8(acc[0][nt], a[0][0], a[0][1], a[0][2], a[0][3], b0, b1);
                mma8(acc[1][nt], a[1][0], a[1][1], a[1][2], a[1][3], b0, b1);
            }
        }
        __syncthreads();
    }

    // Epilogue -> g_o [B*L, C], c = h*64 + d, tf32-rounded for proj
    const int bb = bh / H_;
    const int h = bh % H_;
#pragma unroll
    for (int mt = 0; mt < 2; mt++) {
        int mg = m0 + wm * 32 + mt * 16 + gr;
#pragma unroll
        for (int nt = 0; nt < 4; nt++) {
            int d = wn * 32 + nt * 8 + tc * 2;
            size_t addr = ((size_t)(bb * L_ + mg)) * C_ + h * D_ + d;
            *(float2*)&g_o[addr] = make_float2(f2tf(acc[mt][nt][0]), f2tf(acc[mt][nt][1]));
            *(float2*)&g_o[addr + (size_t)8 * C_] =
                make_float2(f2tf(acc[mt][nt][2]), f2tf(acc[mt][nt][3]));
        }
    }
}

// ---------------------------------------------------------------------------
extern "C" void kernel_launch(void* const* d_in, const int* in_sizes, int n_in,
                              void* d_out, int out_size)
{
    const float* x      = (const float*)d_in[0];
    const float* w_qkv  = (const float*)d_in[1];
    const float* w_proj = (const float*)d_in[2];
    const float* b_proj = (const float*)d_in[3];

    float* out  = (float*)d_out;              // [B,L,C]
    float* attn = out + (size_t)M_ * C_;      // [B,H,L,L]

    const int gemm_smem = 4 * GST * (int)sizeof(float);             // 73728
    const int attn_smem = (2 * KST + 512) * (int)sizeof(float);     // 79872
    const int pv_smem   = 2 * (PAST + PBST) * (int)sizeof(float);   // 55296

    cudaFuncSetAttribute(gemm_tc<0>, cudaFuncAttributeMaxDynamicSharedMemorySize, gemm_smem);
    cudaFuncSetAttribute(gemm_tc<1>, cudaFuncAttributeMaxDynamicSharedMemorySize, gemm_smem);
    cudaFuncSetAttribute(attn_tc, cudaFuncAttributeMaxDynamicSharedMemorySize, attn_smem);
    cudaFuncSetAttribute(pv_tc, cudaFuncAttributeMaxDynamicSharedMemorySize, pv_smem);

    // 0. Pre-round inputs to tf32
    round_tf32<<<(NX4 + NWQ4 + NWP4) / 256, 256>>>(x, w_qkv, w_proj);

    // 1. QKV projection (v stored transposed)
    gemm_tc<0><<<dim3(NQKV_ / 128, M_ / 128), 256, gemm_smem>>>(nullptr, nullptr);

    // 2. Scores + softmax + attn write (register-resident strip)
    attn_tc<<<dim3(L_ / 32, B_ * H_), 512, attn_smem>>>(attn);

    // 3. PV GEMM (reads attn back, rna at load -> numerics match R5)
    pv_tc<<<dim3(L_ / 128, B_ * H_), 256, pv_smem>>>(attn);

    // 4. Output projection + bias
    gemm_tc<1><<<dim3(C_ / 128, M_ / 128), 256, gemm_smem>>>(b_proj, out);
}